// round 3
// baseline (speedup 1.0000x reference)
#include <cuda_runtime.h>
#include <math.h>

#define D 256
#define E 512
#define NTOK (32 * 4096)      // 131072 tokens
#define TM 128                 // tokens per CTA
#define TE 128                 // embed chunk
#define KC 16                  // K stage depth
#define NSTAGE (D / KC)        // 16
#define GRID_MAIN (NTOK / TM)  // 1024
#define SMP (TM + 4)           // smem row pad
#define MAXFLAG 8192
#define GAP_TH 1e-3f

__device__ float g_en[E * D];          // normalized codebook (fp32, fast path)
__device__ float g_et[E * D];          // reference-emulated codebook (division path)
__device__ float g_se[E];              // emulated fp32 sum(et^2) per embed
__device__ float g_partial[GRID_MAIN]; // per-CTA diff partial sums
__device__ int g_cnt;                  // flagged-token count
__device__ int g_list[MAXFLAG];        // flagged token ids

// pack (orderable score << 32) | (~e): atomicMax picks max score, ties -> lowest e
__device__ __forceinline__ unsigned long long packkey(float v, unsigned e) {
    unsigned u = __float_as_uint(v);
    u = (u & 0x80000000u) ? ~u : (u | 0x80000000u);
    return ((unsigned long long)u << 32) | (unsigned long long)(0xFFFFFFFFu - e);
}
__device__ __forceinline__ float unpackscore(unsigned long long k) {
    unsigned u = (unsigned)(k >> 32);
    u = (u & 0x80000000u) ? (u & 0x7FFFFFFFu) : ~u;
    return __uint_as_float(u);
}
__device__ __forceinline__ unsigned unpackind(unsigned long long k) {
    return 0xFFFFFFFFu - (unsigned)k;
}

// ---------------------------------------------------------------------------
// Kernel 1: per-row normalize. Produces BOTH the fast fp32 codebook g_en and
// the reference-emulated codebook g_et (fp64 norm-sum rounded to fp32, then
// fp32 DIVISION per element, matching embed_t / norm(embed_t, axis=0)), plus
// the emulated fp32 sum(et^2) = g_se.
// ---------------------------------------------------------------------------
__global__ __launch_bounds__(256) void normalize_kernel(const float* __restrict__ emb) {
    if (blockIdx.x == 0 && threadIdx.x == 0) g_cnt = 0;
    int wid = threadIdx.x >> 5, lane = threadIdx.x & 31;
    int r = blockIdx.x * 8 + wid;
    const float4* row = (const float4*)(emb + (size_t)r * D);
    float4 v0 = row[lane];
    float4 v1 = row[lane + 32];

    // fp32 fast-path norm
    float ss = v0.x * v0.x + v0.y * v0.y + v0.z * v0.z + v0.w * v0.w
             + v1.x * v1.x + v1.y * v1.y + v1.z * v1.z + v1.w * v1.w;
    // fp64 accurate norm (for the emulated path)
    double dss = (double)v0.x * v0.x + (double)v0.y * v0.y + (double)v0.z * v0.z
               + (double)v0.w * v0.w + (double)v1.x * v1.x + (double)v1.y * v1.y
               + (double)v1.z * v1.z + (double)v1.w * v1.w;
#pragma unroll
    for (int o = 16; o; o >>= 1) {
        ss += __shfl_xor_sync(0xFFFFFFFFu, ss, o);
        dss += __shfl_xor_sync(0xFFFFFFFFu, dss, o);
    }
    float inv = 1.0f / sqrtf(ss);
    float4 n0 = v0, n1 = v1;
    n0.x *= inv; n0.y *= inv; n0.z *= inv; n0.w *= inv;
    n1.x *= inv; n1.y *= inv; n1.z *= inv; n1.w *= inv;
    float4* dst = (float4*)(g_en + (size_t)r * D);
    dst[lane] = n0;
    dst[lane + 32] = n1;

    // emulated path: norm = fl32(sqrt(fl32(sum))) ; et = fl32(emb / norm)
    float nf = sqrtf((float)dss);
    float4 e0, e1;
    e0.x = v0.x / nf; e0.y = v0.y / nf; e0.z = v0.z / nf; e0.w = v0.w / nf;
    e1.x = v1.x / nf; e1.y = v1.y / nf; e1.z = v1.z / nf; e1.w = v1.w / nf;
    float4* dte = (float4*)(g_et + (size_t)r * D);
    dte[lane] = e0;
    dte[lane + 32] = e1;
    double se = (double)e0.x * e0.x + (double)e0.y * e0.y + (double)e0.z * e0.z
              + (double)e0.w * e0.w + (double)e1.x * e1.x + (double)e1.y * e1.y
              + (double)e1.z * e1.z + (double)e1.w * e1.w;
#pragma unroll
    for (int o = 16; o; o >>= 1) se += __shfl_xor_sync(0xFFFFFFFFu, se, o);
    if (lane == 0) g_se[r] = (float)se;
}

// ---------------------------------------------------------------------------
// Kernel 2: GEMM (scores = X @ EnT) with running top-2 per token; epilogue
// gathers out rows, writes indices, partial diff, and flags near-ties.
// ---------------------------------------------------------------------------
__global__ __launch_bounds__(256, 2) void main_kernel(const float* __restrict__ input,
                                                      float* __restrict__ out,
                                                      float* __restrict__ indf) {
    __shared__ float As[2][KC][SMP];
    __shared__ float Bs[2][KC][SMP];
    __shared__ unsigned long long c1[TM], c2[TM];   // per-chunk top1/top2
    __shared__ unsigned long long gb1[TM], gb2[TM]; // running global top1/top2
    __shared__ float wred[8];

    const int tid = threadIdx.x;
    const int tx = tid & 15;
    const int ty = tid >> 4;
    const int m0 = blockIdx.x * TM;

    if (tid < TM) { gb1[tid] = 0ull; gb2[tid] = 0ull; }

    const int r0 = tid >> 2;
    const int kq0 = tid & 3;
    const int kk = kq0 * 4;

    const float* Abase = input + (size_t)m0 * D;

    for (int e0 = 0; e0 < E; e0 += TE) {
        if (tid < TM) { c1[tid] = 0ull; c2[tid] = 0ull; }

        float acc[8][8];
#pragma unroll
        for (int i = 0; i < 8; i++)
#pragma unroll
            for (int j = 0; j < 8; j++) acc[i][j] = 0.0f;

        const float* Bbase = g_en + (size_t)e0 * D;

        float4 ra0 = *(const float4*)(Abase + (size_t)r0 * D + kk);
        float4 ra1 = *(const float4*)(Abase + (size_t)(r0 + 64) * D + kk);
        float4 rb0 = *(const float4*)(Bbase + (size_t)r0 * D + kk);
        float4 rb1 = *(const float4*)(Bbase + (size_t)(r0 + 64) * D + kk);
        As[0][kk + 0][r0] = ra0.x; As[0][kk + 1][r0] = ra0.y;
        As[0][kk + 2][r0] = ra0.z; As[0][kk + 3][r0] = ra0.w;
        As[0][kk + 0][r0 + 64] = ra1.x; As[0][kk + 1][r0 + 64] = ra1.y;
        As[0][kk + 2][r0 + 64] = ra1.z; As[0][kk + 3][r0 + 64] = ra1.w;
        Bs[0][kk + 0][r0] = rb0.x; Bs[0][kk + 1][r0] = rb0.y;
        Bs[0][kk + 2][r0] = rb0.z; Bs[0][kk + 3][r0] = rb0.w;
        Bs[0][kk + 0][r0 + 64] = rb1.x; Bs[0][kk + 1][r0 + 64] = rb1.y;
        Bs[0][kk + 2][r0 + 64] = rb1.z; Bs[0][kk + 3][r0 + 64] = rb1.w;
        __syncthreads();

        int cur = 0;
#pragma unroll 1
        for (int s = 0; s < NSTAGE; s++) {
            if (s + 1 < NSTAGE) {
                int k0 = (s + 1) * KC + kk;
                ra0 = *(const float4*)(Abase + (size_t)r0 * D + k0);
                ra1 = *(const float4*)(Abase + (size_t)(r0 + 64) * D + k0);
                rb0 = *(const float4*)(Bbase + (size_t)r0 * D + k0);
                rb1 = *(const float4*)(Bbase + (size_t)(r0 + 64) * D + k0);
            }
#pragma unroll
            for (int k = 0; k < KC; k++) {
                float4 a0 = *(const float4*)&As[cur][k][ty * 8];
                float4 a1 = *(const float4*)&As[cur][k][ty * 8 + 4];
                float4 b0 = *(const float4*)&Bs[cur][k][tx * 8];
                float4 b1 = *(const float4*)&Bs[cur][k][tx * 8 + 4];
                float a[8] = {a0.x, a0.y, a0.z, a0.w, a1.x, a1.y, a1.z, a1.w};
                float b[8] = {b0.x, b0.y, b0.z, b0.w, b1.x, b1.y, b1.z, b1.w};
#pragma unroll
                for (int i = 0; i < 8; i++)
#pragma unroll
                    for (int j = 0; j < 8; j++)
                        acc[i][j] = fmaf(a[i], b[j], acc[i][j]);
            }
            if (s + 1 < NSTAGE) {
                __syncthreads();
                int nxt = cur ^ 1;
                As[nxt][kk + 0][r0] = ra0.x; As[nxt][kk + 1][r0] = ra0.y;
                As[nxt][kk + 2][r0] = ra0.z; As[nxt][kk + 3][r0] = ra0.w;
                As[nxt][kk + 0][r0 + 64] = ra1.x; As[nxt][kk + 1][r0 + 64] = ra1.y;
                As[nxt][kk + 2][r0 + 64] = ra1.z; As[nxt][kk + 3][r0 + 64] = ra1.w;
                Bs[nxt][kk + 0][r0] = rb0.x; Bs[nxt][kk + 1][r0] = rb0.y;
                Bs[nxt][kk + 2][r0] = rb0.z; Bs[nxt][kk + 3][r0] = rb0.w;
                Bs[nxt][kk + 0][r0 + 64] = rb1.x; Bs[nxt][kk + 1][r0 + 64] = rb1.y;
                Bs[nxt][kk + 2][r0 + 64] = rb1.z; Bs[nxt][kk + 3][r0 + 64] = rb1.w;
                __syncthreads();
                cur = nxt;
            }
        }

        // ---- chunk top-1 (pass A) ----
#pragma unroll
        for (int i = 0; i < 8; i++) {
            float vmax = acc[i][0];
            int jmax = 0;
#pragma unroll
            for (int j = 1; j < 8; j++)
                if (acc[i][j] > vmax) { vmax = acc[i][j]; jmax = j; }
            atomicMax(&c1[ty * 8 + i], packkey(vmax, (unsigned)(e0 + tx * 8 + jmax)));
        }
        __syncthreads();

        // ---- chunk top-2 (pass B: best excluding the chunk winner) ----
#pragma unroll
        for (int i = 0; i < 8; i++) {
            unsigned long long win = c1[ty * 8 + i];
            unsigned long long loc = 0ull;
#pragma unroll
            for (int j = 0; j < 8; j++) {
                unsigned long long k = packkey(acc[i][j], (unsigned)(e0 + tx * 8 + j));
                if (k != win && k > loc) loc = k;
            }
            atomicMax(&c2[ty * 8 + i], loc);
        }
        __syncthreads();

        // ---- merge chunk (c1,c2) into running (gb1,gb2) ----
        if (tid < TM) {
            unsigned long long a = gb1[tid], b = gb2[tid];
            unsigned long long x1 = c1[tid], x2 = c2[tid];
            if (x1 > a) {
                gb1[tid] = x1;
                gb2[tid] = (a > x2) ? a : x2;
            } else {
                gb2[tid] = (b > x1) ? b : x1;
            }
        }
        __syncthreads();
    }

    // flag near-ties for reference-emulating re-scoring
    if (tid < TM) {
        float s1 = unpackscore(gb1[tid]);
        float s2 = unpackscore(gb2[tid]);
        if (s1 - s2 < GAP_TH) {
            int pos = atomicAdd(&g_cnt, 1);
            if (pos < MAXFLAG) g_list[pos] = m0 + tid;
        }
    }
    __syncthreads();

    // epilogue: each warp owns 16 tokens; write out row = en[ind], index, diff
    int wid = tid >> 5, lane = tid & 31;
    float dsum = 0.0f;
#pragma unroll 1
    for (int t = 0; t < 16; t++) {
        int m = wid * 16 + t;
        int ind = (int)unpackind(gb1[m]);
        size_t tok = (size_t)(m0 + m);
        const float4* q4 = (const float4*)(g_en + (size_t)ind * D);
        const float4* x4 = (const float4*)(input + tok * D);
        float4* o4 = (float4*)(out + tok * D);
#pragma unroll
        for (int c = 0; c < 2; c++) {
            int dd = c * 32 + lane;
            float4 q = q4[dd];
            float4 x = x4[dd];
            o4[dd] = q;
            float d0 = q.x - x.x, d1 = q.y - x.y, d2 = q.z - x.z, d3 = q.w - x.w;
            dsum += d0 * d0 + d1 * d1 + d2 * d2 + d3 * d3;
        }
        if (lane == 0) indf[tok] = (float)ind;
    }
#pragma unroll
    for (int o = 16; o; o >>= 1) dsum += __shfl_xor_sync(0xFFFFFFFFu, dsum, o);
    if (lane == 0) wred[wid] = dsum;
    __syncthreads();
    if (tid == 0) {
        float s = 0.0f;
        for (int w = 0; w < 8; w++) s += wred[w];
        g_partial[blockIdx.x] = s;
    }
}

// ---------------------------------------------------------------------------
// Kernel 3: reference-EMULATING re-score of flagged near-tie tokens.
// The reference computes dist = ||x||^2 - 2*(x.et) + ||et||^2 in fp32 at
// magnitude ~257, so the FINAL fp32 rounding quantizes scores to a ~3e-5
// grid; collapsed ties resolve to the LOWEST index (jnp.argmax first-hit).
// We reproduce that: fp64 inner products, then round dist to fp32, then
// argmin(dist) with lowest-index tie-break.
// ---------------------------------------------------------------------------
__global__ __launch_bounds__(256) void refine_kernel(const float* __restrict__ input,
                                                     float* __restrict__ out,
                                                     float* __restrict__ indf) {
    __shared__ float xs[D];
    __shared__ double sred[256];
    __shared__ unsigned long long kred[256];
    __shared__ int s_ind;
    int tid = threadIdx.x;
    int cnt = g_cnt;
    if (cnt > MAXFLAG) cnt = MAXFLAG;

    for (int li = blockIdx.x; li < cnt; li += gridDim.x) {
        int tok = g_list[li];
        xs[tid] = input[(size_t)tok * D + tid];
        __syncthreads();

        // sumx = fl32( fp64 sum of x^2 )  (emulates jnp.sum in fp32 to within
        // ~1e-6, far below the 3e-5 dist ULP)
        double px = (double)xs[tid] * (double)xs[tid];
        sred[tid] = px;
        __syncthreads();
        for (int o = 128; o; o >>= 1) { if (tid < o) sred[tid] += sred[tid + o]; __syncthreads(); }
        float sx_f = (float)sred[0];
        __syncthreads();

        // each thread scores 2 embeds; key = (bits(dist_f32)<<32)|e, minimized
        unsigned long long bestk = 0xFFFFFFFFFFFFFFFFull;
#pragma unroll
        for (int h = 0; h < 2; h++) {
            int e = tid + h * 256;
            const float* er = g_et + (size_t)e * D;
            double dot = 0.0;
            for (int d = 0; d < D; d += 4) {
                float4 ev = *(const float4*)(er + d);
                float4 xv = *(const float4*)(xs + d);
                dot += (double)xv.x * ev.x + (double)xv.y * ev.y
                     + (double)xv.z * ev.z + (double)xv.w * ev.w;
            }
            float dist_f = (float)((double)sx_f - 2.0 * dot + (double)g_se[e]);
            unsigned long long k =
                ((unsigned long long)__float_as_uint(dist_f) << 32) | (unsigned)e;
            if (k < bestk) bestk = k;
        }
        kred[tid] = bestk;
        __syncthreads();
        for (int o = 128; o; o >>= 1) {
            if (tid < o && kred[tid + o] < kred[tid]) kred[tid] = kred[tid + o];
            __syncthreads();
        }
        if (tid == 0) {
            s_ind = (int)(unsigned)kred[0];
            indf[tok] = (float)s_ind;
        }
        __syncthreads();
        int ind = s_ind;
        out[(size_t)tok * D + tid] = g_en[(size_t)ind * D + tid];
        __syncthreads();
    }
}

// ---------------------------------------------------------------------------
// Kernel 4: diff correction for refined tokens + deterministic final loss.
// (refine may change out rows, so recompute diff for flagged tokens here
//  against the ORIGINAL main-kernel partials would double count; instead the
//  main kernel's partial already used its own ind. For flipped tokens the
//  diff changes by < 2*gap ~ 2e-3 absolute out of ~2.6e7 total -> relative
//  effect < 1e-10 on loss; ignore.)
// entropy = 2*E*sum(en^2) - 2*||sum_i en_i||^2
// ---------------------------------------------------------------------------
__global__ __launch_bounds__(256) void finalize_kernel(float* __restrict__ loss_out) {
    __shared__ double red[256];
    int tid = threadIdx.x;

    double ds = 0.0;
    for (int i = tid; i < GRID_MAIN; i += 256) ds += (double)g_partial[i];

    float s = 0.0f, q = 0.0f;
    for (int i = 0; i < E; i++) {
        float v = g_en[i * D + tid];
        s += v;
        q += v * v;
    }
    double vss = (double)s * (double)s;
    double vq = (double)q;

    red[tid] = ds;
    __syncthreads();
    for (int o = 128; o; o >>= 1) { if (tid < o) red[tid] += red[tid + o]; __syncthreads(); }
    double diff_sum = red[0];
    __syncthreads();

    red[tid] = vss;
    __syncthreads();
    for (int o = 128; o; o >>= 1) { if (tid < o) red[tid] += red[tid + o]; __syncthreads(); }
    double ss2 = red[0];
    __syncthreads();

    red[tid] = vq;
    __syncthreads();
    for (int o = 128; o; o >>= 1) { if (tid < o) red[tid] += red[tid + o]; __syncthreads(); }
    double sumsq = red[0];

    if (tid == 0) {
        double entropy = 2.0 * (double)E * sumsq - 2.0 * ss2;
        double diff = diff_sum / ((double)NTOK * (double)D);
        loss_out[0] = (float)(diff - entropy / (512.0 * 512.0));
    }
}

// ---------------------------------------------------------------------------
extern "C" void kernel_launch(void* const* d_in, const int* in_sizes, int n_in,
                              void* d_out, int out_size) {
    const float* input = (const float*)d_in[0];
    const float* emb = (const float*)d_in[1];
    if (n_in >= 2 && in_sizes[0] == E * D && in_sizes[1] == NTOK * D) {
        input = (const float*)d_in[1];
        emb = (const float*)d_in[0];
    }
    float* out = (float*)d_out;                      // [NTOK*D] quantized output
    float* loss = out + (size_t)NTOK * D;            // [1]      scalar loss
    float* indf = loss + 1;                          // [NTOK]   indices (as float)

    normalize_kernel<<<E / 8, 256>>>(emb);
    main_kernel<<<GRID_MAIN, 256>>>(input, out, indf);
    refine_kernel<<<64, 256>>>(input, out, indf);
    finalize_kernel<<<1, 256>>>(loss);
}